// round 7
// baseline (speedup 1.0000x reference)
#include <cuda_runtime.h>
#include <cuda_fp16.h>
#include <cstdint>

// Problem constants (fixed by the dataset)
#define NB 10000     // base mesh vertices
#define MB_ 500000   // target vertices
#define BB 128       // batch of scalar fields

#define NCHUNK 16    // b-chunks of 8
#define BC 8         // b per chunk
#define MSPLITS 37   // 37*16 = 592 blocks = 4 exact waves of 148 SMs
#define MPB 13514    // ceil(500000/37)

// Chunked fp16 field table: g_fT_c[chunk][i][b'] , 16B (uint4) per (chunk,i).
// 16 * 10000 * 8 halves = 2.56 MB (L2-resident).
__device__ __align__(16) __half g_fT_c[NCHUNK * NB * BC];

// Packed per-m record (16B): x = i0 | i1<<16, y = i2, z = bits(w0), w = bits(w1).
// 8 MB (L2-resident across the 16 chunk re-reads).
__device__ __align__(16) uint4 g_recs[MB_];

// ---------------------------------------------------------------------------
// Prepass 1: pack tri_idx + bary_weights into 16B records (one-shot, ~12 MB).
// ---------------------------------------------------------------------------
__global__ __launch_bounds__(256)
void pack_recs_kernel(const int* __restrict__ tri_idx,
                      const float* __restrict__ bary_w) {
    const int m = blockIdx.x * 256 + threadIdx.x;
    if (m >= MB_) return;
    const int i0 = tri_idx[3 * m + 0];
    const int i1 = tri_idx[3 * m + 1];
    const int i2 = tri_idx[3 * m + 2];
    const float w0 = bary_w[3 * m + 0];
    const float w1 = bary_w[3 * m + 1];
    uint4 r;
    r.x = (unsigned)i0 | ((unsigned)i1 << 16);
    r.y = (unsigned)i2;
    r.z = __float_as_uint(w0);
    r.w = __float_as_uint(w1);
    g_recs[m] = r;
}

// ---------------------------------------------------------------------------
// Prepass 2: transpose f (B, N) fp32 -> chunked fp16 g_fT_c[chunk][n][8b].
// Block (32, 32): 32 n x 32 b tile -> 4 local chunks.
// ---------------------------------------------------------------------------
__global__ void transpose_chunked_kernel(const float* __restrict__ f) {
    __shared__ float tile[32][33];
    const int n0 = blockIdx.x * 32;
    const int b0 = blockIdx.y * 32;
    const int tx = threadIdx.x;
    const int ty = threadIdx.y;

    const int n = n0 + tx;
    if (n < NB) {
        tile[ty][tx] = f[(b0 + ty) * NB + n];   // tile[b_local][n_local]
    }
    __syncthreads();

    // 128 write tasks: 4 local chunks x 32 n, one uint4 (8 halves) each.
    const int tid = ty * 32 + tx;
    if (tid < 128) {
        const int cl = tid >> 5;       // local chunk 0..3
        const int nn = tid & 31;       // n within tile
        const int gn = n0 + nn;
        if (gn < NB) {
            __half h[8];
            #pragma unroll
            for (int j = 0; j < 8; j++) {
                h[j] = __float2half_rn(tile[cl * 8 + j][nn]);
            }
            const int chunk = (b0 >> 3) + cl;
            ((uint4*)g_fT_c)[(size_t)chunk * NB + gn] = *(const uint4*)h;
        }
    }
}

// ---------------------------------------------------------------------------
// Main kernel: grid (MSPLITS, NCHUNK), 1024 threads, 160 KB dynamic smem.
//   Stage the chunk's full fT slice (10000 x 8 fp16 = 160 KB) in smem, then
//   stream the block's m-range: 1 LDG.128 record + 3 LDS.128 gathers +
//   fp32 FMA + 8 coalesced STG.32 (lane = m).
//   Gathers never touch L2; records + slice fills are L2-resident.
// ---------------------------------------------------------------------------
__global__ __launch_bounds__(1024, 1)
void bary_chunk_kernel(float* __restrict__ out) {
    extern __shared__ __align__(16) unsigned char smem_raw[];
    uint4* fT_s = (uint4*)smem_raw;          // NB entries x 16B = 160000 B

    const int tid   = threadIdx.x;
    const int chunk = blockIdx.y;

    // Fill slice: 160 KB contiguous, fully coalesced.
    const uint4* src = (const uint4*)g_fT_c + (size_t)chunk * NB;
    for (int i = tid; i < NB; i += 1024) {
        fT_s[i] = src[i];
    }
    __syncthreads();

    const int m0   = blockIdx.x * MPB;
    const int mend = (m0 + MPB < MB_) ? (m0 + MPB) : MB_;
    const long obase = (long)(chunk * BC) * MB_;

    for (int m = m0 + tid; m < mend; m += 1024) {
        const uint4 rec = __ldg(&g_recs[m]);
        const int i0 = rec.x & 0xFFFF;
        const int i1 = rec.x >> 16;
        const int i2 = rec.y;
        const float w0 = __uint_as_float(rec.z);
        const float w1 = __uint_as_float(rec.w);
        const float w2 = 1.0f - w0 - w1;

        const uint4 A = fT_s[i0];
        const uint4 Bv = fT_s[i1];
        const uint4 C = fT_s[i2];
        const unsigned* au = (const unsigned*)&A;
        const unsigned* bu = (const unsigned*)&Bv;
        const unsigned* cu = (const unsigned*)&C;

        float r[8];
        #pragma unroll
        for (int j = 0; j < 4; j++) {
            const float2 fa = __half22float2(*(const __half2*)&au[j]);
            const float2 fb = __half22float2(*(const __half2*)&bu[j]);
            const float2 fc = __half22float2(*(const __half2*)&cu[j]);
            r[2 * j + 0] = fmaf(w0, fa.x, fmaf(w1, fb.x, w2 * fc.x));
            r[2 * j + 1] = fmaf(w0, fa.y, fmaf(w1, fb.y, w2 * fc.y));
        }

        #pragma unroll
        for (int j = 0; j < 8; j++) {
            out[obase + (long)j * MB_ + m] = r[j];
        }
    }
}

// ---------------------------------------------------------------------------
// Launch
// ---------------------------------------------------------------------------
extern "C" void kernel_launch(void* const* d_in, const int* in_sizes, int n_in,
                              void* d_out, int out_size) {
    const float* f   = (const float*)d_in[0];   // (128, 10000) f32
    const int*   tri = (const int*)  d_in[1];   // (500000, 3) i32
    const float* bw  = (const float*)d_in[2];   // (500000, 3) f32
    float* out = (float*)d_out;                  // (128, 500000) f32

    // Unconditional (idempotent, capture-legal, no static guard — harness
    // rule: kernel_launch must be deterministic with no static state).
    cudaFuncSetAttribute(bary_chunk_kernel,
                         cudaFuncAttributeMaxDynamicSharedMemorySize,
                         NB * 16);

    // Prepass 1: pack records
    pack_recs_kernel<<<(MB_ + 255) / 256, 256>>>(tri, bw);

    // Prepass 2: chunked fp16 transpose
    {
        dim3 block(32, 32);
        dim3 grid((NB + 31) / 32, BB / 32);
        transpose_chunked_kernel<<<grid, block>>>(f);
    }

    // Main: (37 m-splits x 16 b-chunks) = 592 blocks = 4 exact waves
    {
        dim3 grid(MSPLITS, NCHUNK);
        bary_chunk_kernel<<<grid, 1024, NB * 16>>>(out);
    }
}